// round 9
// baseline (speedup 1.0000x reference)
#include <cuda_runtime.h>

// Ping-pong scratch (device globals — no allocation allowed).
__device__ float g_buf1[4 * 3 * 96  * 128];   // stage1 out
__device__ float g_buf2[4 * 3 * 192 * 256];   // stage2 out
__device__ float g_buf3[4 * 3 * 384 * 512];   // stage3 out

#define CP_ASYNC4(dst, src) \
    asm volatile("cp.async.ca.shared.global [%0], [%1], 4;\n" :: "r"(dst), "l"(src))
#define CP_COMMIT() asm volatile("cp.async.commit_group;\n")
#define CP_WAIT(N)  asm volatile("cp.async.wait_group %0;\n" :: "n"(N) : "memory")

// One convex-upsample stage (scale=2). Thread = one SOURCE pixel (n,h,w),
// producing the 2x2 output quad for all 3 channels.
// The 36 per-thread mask loads (the DRAM stream) are issued as cp.async into a
// per-thread smem slot (smk[c][tid]) — all 36 in flight with zero register
// cost — committed one group per 3x3 tap k, and consumed with staged
// wait_group so tap-k compute overlaps tap-(k+1..8) DRAM fills.
// Neighbor gathers preloaded per row-of-3-taps (9 regs) ahead of each wait.
// Softmax over k without max-subtraction (exp of ~N(0,1) safe; identical).
template<int H, int WSHIFT, bool FIRST, int TPB, int MINB>
__global__ __launch_bounds__(TPB, MINB)
void convex_up_async(const float* __restrict__ in_flow,
                     const float* __restrict__ in_dz,
                     const float* __restrict__ mask,
                     float* __restrict__ out)
{
    constexpr int W  = 1 << WSHIFT;
    constexpr int HW = H * W;

    __shared__ float smk[36][TPB];

    const int tid = threadIdx.x;
    const int idx = blockIdx.x * TPB + tid;   // grid exact: no guard
    const int n = blockIdx.y;
    const int w = idx & (W - 1);
    const int h = idx >> WSHIFT;

    const float* mb = mask + (size_t)n * (36 * HW) + idx;   // + c*HW per channel
    const float* pf = in_flow + (size_t)n * (FIRST ? 2 * HW : 3 * HW);
    const float* pd = in_dz   + (size_t)n * (FIRST ?     HW : 3 * HW);

    // ---- async prologue: stage all 36 mask values, one commit group per tap k
    const unsigned sbase = (unsigned)__cvta_generic_to_shared(&smk[0][tid]);
#pragma unroll
    for (int k = 0; k < 9; k++) {
#pragma unroll
        for (int q = 0; q < 4; q++) {
            const int c = k * 4 + q;
            CP_ASYNC4(sbase + c * (TPB * 4), mb + (size_t)c * HW);
        }
        CP_COMMIT();
    }

    // Hoisted edge predicates.
    const bool okl = (w > 0), okr = (w + 1 < W);
    const bool oku = (h > 0), okd = (h + 1 < H);

    float sum[4];
    float acc[4][3];
#pragma unroll
    for (int q = 0; q < 4; q++) {
        sum[q] = 0.f;
        acc[q][0] = acc[q][1] = acc[q][2] = 0.f;
    }

    // ---- main loop: 3 rows of 3 taps; gathers batched per row before the wait
#pragma unroll
    for (int r = 0; r < 3; r++) {
        const int dy = r - 1;
        const bool rok = (dy == 0) || (dy < 0 ? oku : okd);

        float rv[3][3];   // rv[dx][ch]
#pragma unroll
        for (int dxi = 0; dxi < 3; dxi++) {
            const int dx = dxi - 1;
            const bool ok = rok && (dx == 0 || (dx < 0 ? okl : okr));
            if (ok) {
                const int off = ((h + dy) << WSHIFT) + (w + dx);
                rv[dxi][0] = pf[off];
                rv[dxi][1] = pf[off + HW];
                rv[dxi][2] = pd[off];
            } else {
                rv[dxi][0] = rv[dxi][1] = rv[dxi][2] = 0.f;
            }
        }

        // groups 0 .. 3r+2 must be complete -> allow 6-3r outstanding
        if (r == 0)      CP_WAIT(6);
        else if (r == 1) CP_WAIT(3);
        else             CP_WAIT(0);

#pragma unroll
        for (int kk = 0; kk < 3; kk++) {
            const int k = r * 3 + kk;
#pragma unroll
            for (int q = 0; q < 4; q++) {
                float e = __expf(smk[k * 4 + q][tid]);
                sum[q] += e;
                acc[q][0] = fmaf(e, rv[kk][0], acc[q][0]);
                acc[q][1] = fmaf(e, rv[kk][1], acc[q][1]);
                acc[q][2] = fmaf(e, rv[kk][2], acc[q][2]);
            }
        }
    }

    float inv[4];
#pragma unroll
    for (int q = 0; q < 4; q++) inv[q] = __fdividef(1.0f, sum[q]);

    // out [N,3,2H,2W]; quad q = i*2+j -> pixel (2h+i, 2w+j). float2 stores.
    constexpr int W2 = W << 1;
    constexpr size_t HW4 = (size_t)HW * 4;
    float* ob = out + (size_t)n * (3 * HW4)
                    + ((size_t)h << (WSHIFT + 2)) + (w << 1);
#pragma unroll
    for (int ch = 0; ch < 3; ch++) {
        const float pm = (ch < 2) ? 2.0f : 1.0f;   // flow premul per stage
#pragma unroll
        for (int i = 0; i < 2; i++) {
            float2 v;
            v.x = pm * acc[i * 2 + 0][ch] * inv[i * 2 + 0];
            v.y = pm * acc[i * 2 + 1][ch] * inv[i * 2 + 1];
            *reinterpret_cast<float2*>(ob + (size_t)ch * HW4 + (size_t)i * W2) = v;
        }
    }
}

template<int H, int WSHIFT, bool FIRST, int TPB, int MINB>
static inline void launch_stage(const float* pf, const float* pd,
                                const float* mask, float* out, int N)
{
    constexpr int HW = H << WSHIFT;
    static_assert(HW % TPB == 0, "exact grid");
    dim3 grid(HW / TPB, N);
    convex_up_async<H, WSHIFT, FIRST, TPB, MINB><<<grid, TPB>>>(pf, pd, mask, out);
}

extern "C" void kernel_launch(void* const* d_in, const int* in_sizes, int n_in,
                              void* d_out, int out_size)
{
    const float* flow16 = (const float*)d_in[0];  // [4,2,48,64]
    const float* dz16   = (const float*)d_in[1];  // [4,1,48,64]
    const float* mask16 = (const float*)d_in[2];  // [4,36,48,64]
    const float* mask4  = (const float*)d_in[4];  // [4,36,192,256]
    const float* mask8  = (const float*)d_in[3];  // [4,36,96,128]
    const float* mask2  = (const float*)d_in[5];  // [4,36,384,512]
    float* out = (float*)d_out;                   // [4,3,768,1024]

    float *buf1, *buf2, *buf3;
    cudaGetSymbolAddress((void**)&buf1, g_buf1);
    cudaGetSymbolAddress((void**)&buf2, g_buf2);
    cudaGetSymbolAddress((void**)&buf3, g_buf3);

    const int N = 4;

    // Stage 1: 48x64 -> 96x128. 64-thr blocks -> 192 CTAs (fill the chip).
    launch_stage<48, 6, true, 64, 16>(flow16, dz16, mask16, buf1, N);
    // Stage 2: 96x128 -> 192x256. 64-thr blocks -> 768 CTAs.
    launch_stage<96, 7, false, 64, 16>(buf1, buf1 + 2 * 96 * 128, mask8, buf2, N);
    // Stage 3: 192x256 -> 384x512.
    launch_stage<192, 8, false, 256, 5>(buf2, buf2 + 2 * 192 * 256, mask4, buf3, N);
    // Stage 4: 384x512 -> 768x1024.
    launch_stage<384, 9, false, 256, 5>(buf3, buf3 + 2 * 384 * 512, mask2, out, N);
}

// round 10
// speedup vs baseline: 1.0396x; 1.0396x over previous
#include <cuda_runtime.h>

// Ping-pong scratch (device globals — no allocation allowed).
__device__ float g_buf1[4 * 3 * 96  * 128];   // stage1 out
__device__ float g_buf2[4 * 3 * 192 * 256];   // stage2 out
__device__ float g_buf3[4 * 3 * 384 * 512];   // stage3 out

__device__ __forceinline__ void pdl_trigger() {
    asm volatile("griddepcontrol.launch_dependents;" ::: "memory");
}
__device__ __forceinline__ void pdl_wait() {
    asm volatile("griddepcontrol.wait;" ::: "memory");
}

// One convex-upsample stage (scale=2). Thread = one SOURCE pixel (n,h,w),
// producing the 2x2 output quad for all 3 channels. PDL-pipelined:
//   phase 1 (before griddepcontrol.wait): stream the 36 mask values (which do
//     NOT depend on the producer) and compute softmax denominators — overlaps
//     this stage's mask DRAM traffic with the producer's execution;
//   phase 2 (after wait): gather producer 3x3 neighbors, re-read masks
//     (L2-hot) recomputing exp (bit-identical), accumulate, store.
// mask layout [N,36,H,W], channel c = k*4 + i*2 + j.
// Softmax over k without max-subtraction (exp of ~N(0,1) safe; identical).
template<int H, int WSHIFT, bool FIRST, int TPB, int MINB, bool WAIT>
__global__ __launch_bounds__(TPB, MINB)
void convex_up_pdl(const float* __restrict__ in_flow,
                   const float* __restrict__ in_dz,
                   const float* __restrict__ mask,
                   float* __restrict__ out)
{
    constexpr int W  = 1 << WSHIFT;
    constexpr int HW = H * W;

    pdl_trigger();   // release our dependent stage immediately (single-wave grids)

    const int idx = blockIdx.x * TPB + threadIdx.x;   // grid exact: no guard
    const int n = blockIdx.y;
    const int w = idx & (W - 1);
    const int h = idx >> WSHIFT;

    const float* mb = mask + (size_t)n * (36 * HW) + idx;   // + c*HW per channel
    const float* pf = in_flow + (size_t)n * (FIRST ? 2 * HW : 3 * HW);
    const float* pd = in_dz   + (size_t)n * (FIRST ?     HW : 3 * HW);

    // ---- PHASE 1: mask prefetch + softmax denominators (producer-independent)
    float sum[4] = {0.f, 0.f, 0.f, 0.f};
#pragma unroll
    for (int k = 0; k < 9; k++) {
#pragma unroll
        for (int q = 0; q < 4; q++) {
            sum[q] += __expf(__ldcg(mb + (size_t)(k * 4 + q) * HW));
        }
    }
    float inv[4];
#pragma unroll
    for (int q = 0; q < 4; q++) inv[q] = __fdividef(1.0f, sum[q]);

    // ---- dependency: producer output (pf/pd) must be complete past this point
    if (WAIT) pdl_wait();

    // Hoisted edge predicates.
    const bool okl = (w > 0), okr = (w + 1 < W);
    const bool oku = (h > 0), okd = (h + 1 < H);

    float acc[4][3];
#pragma unroll
    for (int q = 0; q < 4; q++) acc[q][0] = acc[q][1] = acc[q][2] = 0.f;

    // ---- PHASE 2: gathers + exp recompute (masks now L2-hot) + accumulate
#pragma unroll
    for (int k = 0; k < 9; k++) {
        const int dy = k / 3 - 1;
        const int dx = k % 3 - 1;
        const bool ok = (dy == 0 || (dy < 0 ? oku : okd)) &&
                        (dx == 0 || (dx < 0 ? okl : okr));
        float v0 = 0.f, v1 = 0.f, v2 = 0.f;
        if (ok) {
            const int off = ((h + dy) << WSHIFT) + (w + dx);
            v0 = pf[off];
            v1 = pf[off + HW];
            v2 = pd[off];
        }
#pragma unroll
        for (int q = 0; q < 4; q++) {
            float e = __expf(__ldcg(mb + (size_t)(k * 4 + q) * HW));
            acc[q][0] = fmaf(e, v0, acc[q][0]);
            acc[q][1] = fmaf(e, v1, acc[q][1]);
            acc[q][2] = fmaf(e, v2, acc[q][2]);
        }
    }

    // out [N,3,2H,2W]; quad q = i*2+j -> pixel (2h+i, 2w+j). float2 stores.
    constexpr int W2 = W << 1;
    constexpr size_t HW4 = (size_t)HW * 4;
    float* ob = out + (size_t)n * (3 * HW4)
                    + ((size_t)h << (WSHIFT + 2)) + (w << 1);
#pragma unroll
    for (int ch = 0; ch < 3; ch++) {
        const float pm = (ch < 2) ? 2.0f : 1.0f;   // flow premul per stage
#pragma unroll
        for (int i = 0; i < 2; i++) {
            float2 v;
            v.x = pm * acc[i * 2 + 0][ch] * inv[i * 2 + 0];
            v.y = pm * acc[i * 2 + 1][ch] * inv[i * 2 + 1];
            *reinterpret_cast<float2*>(ob + (size_t)ch * HW4 + (size_t)i * W2) = v;
        }
    }
}

template<int H, int WSHIFT, bool FIRST, int TPB, int MINB, bool WAIT>
static inline void launch_stage(const float* pf, const float* pd,
                                const float* mask, float* out, int N)
{
    constexpr int HW = H << WSHIFT;
    static_assert(HW % TPB == 0, "exact grid");

    cudaLaunchConfig_t cfg = {};
    cfg.gridDim  = dim3(HW / TPB, N);
    cfg.blockDim = dim3(TPB);
    cudaLaunchAttribute attr[1];
    attr[0].id = cudaLaunchAttributeProgrammaticStreamSerialization;
    attr[0].val.programmaticStreamSerializationAllowed = 1;
    if (WAIT) { cfg.attrs = attr; cfg.numAttrs = 1; }

    cudaLaunchKernelEx(&cfg, convex_up_pdl<H, WSHIFT, FIRST, TPB, MINB, WAIT>,
                       pf, pd, mask, out);
}

extern "C" void kernel_launch(void* const* d_in, const int* in_sizes, int n_in,
                              void* d_out, int out_size)
{
    const float* flow16 = (const float*)d_in[0];  // [4,2,48,64]
    const float* dz16   = (const float*)d_in[1];  // [4,1,48,64]
    const float* mask16 = (const float*)d_in[2];  // [4,36,48,64]
    const float* mask8  = (const float*)d_in[3];  // [4,36,96,128]
    const float* mask4  = (const float*)d_in[4];  // [4,36,192,256]
    const float* mask2  = (const float*)d_in[5];  // [4,36,384,512]
    float* out = (float*)d_out;                   // [4,3,768,1024]

    float *buf1, *buf2, *buf3;
    cudaGetSymbolAddress((void**)&buf1, g_buf1);
    cudaGetSymbolAddress((void**)&buf2, g_buf2);
    cudaGetSymbolAddress((void**)&buf3, g_buf3);

    const int N = 4;

    // Stage 1: 48x64 -> 96x128. Plain launch (inputs are harness-owned).
    launch_stage<48, 6, true, 64, 8, false>(flow16, dz16, mask16, buf1, N);
    // Stage 2: 96x128 -> 192x256. PDL: prefetch mask8 during stage 1.
    launch_stage<96, 7, false, 64, 8, true>(buf1, buf1 + 2 * 96 * 128,
                                            mask8, buf2, N);
    // Stage 3: 192x256 -> 384x512. PDL: prefetch mask4 during stage 2.
    launch_stage<192, 8, false, 256, 5, true>(buf2, buf2 + 2 * 192 * 256,
                                              mask4, buf3, N);
    // Stage 4: 384x512 -> 768x1024. PDL: prefetch mask2 during stages 2-3.
    launch_stage<384, 9, false, 256, 5, true>(buf3, buf3 + 2 * 384 * 512,
                                              mask2, out, N);
}

// round 12
// speedup vs baseline: 1.1246x; 1.0817x over previous
#include <cuda_runtime.h>

// Ping-pong scratch (device globals — no allocation allowed).
__device__ float g_buf1[4 * 3 * 96  * 128];   // stage1 out
__device__ float g_buf2[4 * 3 * 192 * 256];   // stage2 out
__device__ float g_buf3[4 * 3 * 384 * 512];   // stage3 out

// One convex-upsample stage (scale=2). Block = TPB contiguous source pixels of
// ONE row (W % TPB == 0); thread = one source pixel, producing its 2x2 output
// quad for all 3 channels.
// The 3-row x (TPB+2) x 3-channel input neighborhood is staged in shared
// memory (cooperative coalesced fill, each value loaded once per block), so
// the k-loop's only long-latency ops are the 36 independent mask LDGs —
// maximizing how deep the DRAM mask stream can be batched per warp.
// mask layout [N,36,H,W], channel c = k*4 + i*2 + j.
// Softmax over k without max-subtraction (exp of ~N(0,1) safe; identical).
template<int H, int WSHIFT, bool FIRST, int TPB, int MINB>
__global__ __launch_bounds__(TPB, MINB)
void convex_up_tile(const float* __restrict__ in_flow,
                    const float* __restrict__ in_dz,
                    const float* __restrict__ mask,
                    float* __restrict__ out)
{
    constexpr int W  = 1 << WSHIFT;
    constexpr int HW = H * W;
    constexpr int TC = TPB + 2;          // tile columns (with halo)

    __shared__ float tile[3][3][TC];     // [row r][channel][col]

    const int tid = threadIdx.x;
    const int idx = blockIdx.x * TPB + tid;          // grid exact: no guard
    const int n  = blockIdx.y;
    const int w0 = (blockIdx.x * TPB) & (W - 1);     // block never crosses a row
    const int h  = (blockIdx.x * TPB) >> WSHIFT;
    const int w  = w0 + tid;

    const float* mb = mask + (size_t)n * (36 * HW) + idx;   // + c*HW per channel
    const float* pf = in_flow + (size_t)n * (FIRST ? 2 * HW : 3 * HW);
    const float* pd = in_dz   + (size_t)n * (FIRST ?     HW : 3 * HW);

    // ---- cooperative tile fill: 9 segments of TC coalesced values ----
#pragma unroll
    for (int e = 0; e < 9 * TC; e += TPB) {
        const int ei = e + tid;
        if (ei < 9 * TC) {
            const int r   = ei / (3 * TC);
            const int rem = ei - r * (3 * TC);
            const int ch  = rem / TC;
            const int c   = rem - ch * TC;
            const int hh = h - 1 + r;
            const int ww = w0 - 1 + c;
            float v = 0.f;
            if (hh >= 0 && hh < H && ww >= 0 && ww < W) {
                const float* p = (ch == 0) ? pf : (ch == 1) ? (pf + HW) : pd;
                v = p[(hh << WSHIFT) + ww];
            }
            tile[r][ch][c] = v;
        }
    }
    __syncthreads();

    float sum[4];
    float acc[4][3];
#pragma unroll
    for (int q = 0; q < 4; q++) {
        sum[q] = 0.f;
        acc[q][0] = acc[q][1] = acc[q][2] = 0.f;
    }

    // ---- main loop: mask LDGs are the only long-latency ops ----
#pragma unroll
    for (int k = 0; k < 9; k++) {
        const int dy = k / 3;           // 0..2 -> tile row
        const int dx = k % 3;           // 0..2 -> tile col offset
        const float v0 = tile[dy][0][tid + dx];
        const float v1 = tile[dy][1][tid + dx];
        const float v2 = tile[dy][2][tid + dx];
#pragma unroll
        for (int q = 0; q < 4; q++) {
            float e = __expf(__ldcs(mb + (size_t)(k * 4 + q) * HW));
            sum[q] += e;
            acc[q][0] = fmaf(e, v0, acc[q][0]);
            acc[q][1] = fmaf(e, v1, acc[q][1]);
            acc[q][2] = fmaf(e, v2, acc[q][2]);
        }
    }

    float inv[4];
#pragma unroll
    for (int q = 0; q < 4; q++) inv[q] = __fdividef(1.0f, sum[q]);

    // out [N,3,2H,2W]; quad q = i*2+j -> pixel (2h+i, 2w+j). float2 stores.
    constexpr int W2 = W << 1;
    constexpr size_t HW4 = (size_t)HW * 4;
    float* ob = out + (size_t)n * (3 * HW4)
                    + ((size_t)h << (WSHIFT + 2)) + (w << 1);
#pragma unroll
    for (int ch = 0; ch < 3; ch++) {
        const float pm = (ch < 2) ? 2.0f : 1.0f;   // flow premul per stage
#pragma unroll
        for (int i = 0; i < 2; i++) {
            float2 v;
            v.x = pm * acc[i * 2 + 0][ch] * inv[i * 2 + 0];
            v.y = pm * acc[i * 2 + 1][ch] * inv[i * 2 + 1];
            *reinterpret_cast<float2*>(ob + (size_t)ch * HW4 + (size_t)i * W2) = v;
        }
    }
}

template<int H, int WSHIFT, bool FIRST, int TPB, int MINB>
static inline void launch_stage(const float* pf, const float* pd,
                                const float* mask, float* out, int N)
{
    constexpr int HW = H << WSHIFT;
    static_assert(HW % TPB == 0 && (1 << WSHIFT) % TPB == 0, "row-aligned blocks");
    dim3 grid(HW / TPB, N);
    convex_up_tile<H, WSHIFT, FIRST, TPB, MINB><<<grid, TPB>>>(pf, pd, mask, out);
}

extern "C" void kernel_launch(void* const* d_in, const int* in_sizes, int n_in,
                              void* d_out, int out_size)
{
    const float* flow16 = (const float*)d_in[0];  // [4,2,48,64]
    const float* dz16   = (const float*)d_in[1];  // [4,1,48,64]
    const float* mask16 = (const float*)d_in[2];  // [4,36,48,64]
    const float* mask8  = (const float*)d_in[3];  // [4,36,96,128]
    const float* mask4  = (const float*)d_in[4];  // [4,36,192,256]
    const float* mask2  = (const float*)d_in[5];  // [4,36,384,512]
    float* out = (float*)d_out;                   // [4,3,768,1024]

    float *buf1, *buf2, *buf3;
    cudaGetSymbolAddress((void**)&buf1, g_buf1);
    cudaGetSymbolAddress((void**)&buf2, g_buf2);
    cudaGetSymbolAddress((void**)&buf3, g_buf3);

    const int N = 4;

    // Stage 1: 48x64 -> 96x128. 64-thr blocks (one row) -> 192 CTAs.
    launch_stage<48, 6, true, 64, 8>(flow16, dz16, mask16, buf1, N);
    // Stage 2: 96x128 -> 192x256. 128-thr blocks (one row) -> 384 CTAs.
    launch_stage<96, 7, false, 128, 8>(buf1, buf1 + 2 * 96 * 128, mask8, buf2, N);
    // Stage 3: 192x256 -> 384x512. 256-thr blocks (one row).
    launch_stage<192, 8, false, 256, 5>(buf2, buf2 + 2 * 192 * 256, mask4, buf3, N);
    // Stage 4: 384x512 -> 768x1024. 256-thr blocks (half row).
    launch_stage<384, 9, false, 256, 5>(buf3, buf3 + 2 * 384 * 512, mask2, out, N);
}

// round 13
// speedup vs baseline: 1.2273x; 1.0914x over previous
#include <cuda_runtime.h>

// Ping-pong scratch (device globals — no allocation allowed).
__device__ float g_buf1[4 * 3 * 96  * 128];   // stage1 out
__device__ float g_buf2[4 * 3 * 192 * 256];   // stage2 out
__device__ float g_buf3[4 * 3 * 384 * 512];   // stage3 out

__device__ __forceinline__ void pdl_trigger() {
    asm volatile("griddepcontrol.launch_dependents;" ::: "memory");
}
__device__ __forceinline__ void pdl_wait() {
    asm volatile("griddepcontrol.wait;" ::: "memory");
}

// One convex-upsample stage (scale=2). Thread = one SOURCE pixel (n,h,w),
// producing the 2x2 output quad for all 3 channels. (R7 structure — proven.)
// PDL is used ONLY for tail/head overlap: producers trigger at entry,
// consumers wait at the top before touching producer data. No re-reads,
// no restructuring — per-kernel memory behavior identical to R7.
// mask layout [N,36,H,W], channel c = k*4 + i*2 + j.
// Softmax over k without max-subtraction (exp of ~N(0,1) safe; identical).
template<int H, int WSHIFT, bool FIRST, int TPB, int MINB, bool WAIT, bool TRIG>
__global__ __launch_bounds__(TPB, MINB)
void convex_up_quad(const float* __restrict__ in_flow,
                    const float* __restrict__ in_dz,
                    const float* __restrict__ mask,
                    float* __restrict__ out)
{
    constexpr int W  = 1 << WSHIFT;
    constexpr int HW = H * W;

    if (TRIG) pdl_trigger();   // release dependent stage's CTAs into free slots

    const int idx = blockIdx.x * TPB + threadIdx.x;   // grid exact: no guard
    const int n = blockIdx.y;
    const int w = idx & (W - 1);
    const int h = idx >> WSHIFT;

    const float* mb = mask + (size_t)n * (36 * HW) + idx;   // + c*HW per channel
    const float* pf = in_flow + (size_t)n * (FIRST ? 2 * HW : 3 * HW);
    const float* pd = in_dz   + (size_t)n * (FIRST ?     HW : 3 * HW);

    // Hoisted edge predicates.
    const bool okl = (w > 0), okr = (w + 1 < W);
    const bool oku = (h > 0), okd = (h + 1 < H);

    // Block until producer grid complete (memory visible). Everything above
    // is producer-independent.
    if (WAIT) pdl_wait();

    float sum[4];
    float acc[4][3];
#pragma unroll
    for (int q = 0; q < 4; q++) {
        sum[q] = 0.f;
        acc[q][0] = acc[q][1] = acc[q][2] = 0.f;
    }

#pragma unroll
    for (int k = 0; k < 9; k++) {
        const int dy = k / 3 - 1;
        const int dx = k % 3 - 1;
        const bool ok = (dy == 0 || (dy < 0 ? oku : okd)) &&
                        (dx == 0 || (dx < 0 ? okl : okr));
        float v0 = 0.f, v1 = 0.f, v2 = 0.f;
        if (ok) {
            const int off = ((h + dy) << WSHIFT) + (w + dx);
            v0 = pf[off];
            v1 = pf[off + HW];
            v2 = pd[off];
        }
#pragma unroll
        for (int q = 0; q < 4; q++) {
            float e = __expf(__ldcs(mb + (size_t)(k * 4 + q) * HW));
            sum[q] += e;
            acc[q][0] = fmaf(e, v0, acc[q][0]);
            acc[q][1] = fmaf(e, v1, acc[q][1]);
            acc[q][2] = fmaf(e, v2, acc[q][2]);
        }
    }

    float inv[4];
#pragma unroll
    for (int q = 0; q < 4; q++) inv[q] = __fdividef(1.0f, sum[q]);

    // out [N,3,2H,2W]; quad q = i*2+j -> pixel (2h+i, 2w+j). float2 stores.
    constexpr int W2 = W << 1;
    constexpr size_t HW4 = (size_t)HW * 4;
    float* ob = out + (size_t)n * (3 * HW4)
                    + ((size_t)h << (WSHIFT + 2)) + (w << 1);
#pragma unroll
    for (int ch = 0; ch < 3; ch++) {
        const float pm = (ch < 2) ? 2.0f : 1.0f;   // flow premul per stage
#pragma unroll
        for (int i = 0; i < 2; i++) {
            float2 v;
            v.x = pm * acc[i * 2 + 0][ch] * inv[i * 2 + 0];
            v.y = pm * acc[i * 2 + 1][ch] * inv[i * 2 + 1];
            *reinterpret_cast<float2*>(ob + (size_t)ch * HW4 + (size_t)i * W2) = v;
        }
    }
}

template<int H, int WSHIFT, bool FIRST, int TPB, int MINB, bool WAIT, bool TRIG>
static inline void launch_stage(const float* pf, const float* pd,
                                const float* mask, float* out, int N)
{
    constexpr int HW = H << WSHIFT;
    static_assert(HW % TPB == 0, "exact grid");

    cudaLaunchConfig_t cfg = {};
    cfg.gridDim  = dim3(HW / TPB, N);
    cfg.blockDim = dim3(TPB);
    cudaLaunchAttribute attr[1];
    attr[0].id = cudaLaunchAttributeProgrammaticStreamSerialization;
    attr[0].val.programmaticStreamSerializationAllowed = 1;
    if (WAIT) { cfg.attrs = attr; cfg.numAttrs = 1; }

    cudaLaunchKernelEx(&cfg,
                       convex_up_quad<H, WSHIFT, FIRST, TPB, MINB, WAIT, TRIG>,
                       pf, pd, mask, out);
}

extern "C" void kernel_launch(void* const* d_in, const int* in_sizes, int n_in,
                              void* d_out, int out_size)
{
    const float* flow16 = (const float*)d_in[0];  // [4,2,48,64]
    const float* dz16   = (const float*)d_in[1];  // [4,1,48,64]
    const float* mask16 = (const float*)d_in[2];  // [4,36,48,64]
    const float* mask8  = (const float*)d_in[3];  // [4,36,96,128]
    const float* mask4  = (const float*)d_in[4];  // [4,36,192,256]
    const float* mask2  = (const float*)d_in[5];  // [4,36,384,512]
    float* out = (float*)d_out;                   // [4,3,768,1024]

    float *buf1, *buf2, *buf3;
    cudaGetSymbolAddress((void**)&buf1, g_buf1);
    cudaGetSymbolAddress((void**)&buf2, g_buf2);
    cudaGetSymbolAddress((void**)&buf3, g_buf3);

    const int N = 4;

    // Stage 1: trigger only (inputs harness-owned).
    launch_stage<48, 6, true, 64, 8, false, true>(flow16, dz16, mask16, buf1, N);
    // Stage 2: wait on stage 1, trigger stage 3.
    launch_stage<96, 7, false, 64, 8, true, true>(buf1, buf1 + 2 * 96 * 128,
                                                  mask8, buf2, N);
    // Stage 3: wait on stage 2, trigger stage 4.
    launch_stage<192, 8, false, 256, 5, true, true>(buf2, buf2 + 2 * 192 * 256,
                                                    mask4, buf3, N);
    // Stage 4: wait on stage 3, no trigger (last).
    launch_stage<384, 9, false, 256, 5, true, false>(buf3, buf3 + 2 * 384 * 512,
                                                     mask2, out, N);
}